// round 5
// baseline (speedup 1.0000x reference)
#include <cuda_runtime.h>

// Fixed problem dims
#define NB 4
#define NQv 512
#define MMv 512
#define DDv 256
#define HHv 256

// Scratch (device globals: no allocations allowed)
__device__ float g_q[NB * NQv * HHv];    // projected q, [b*NQ+n][h]
__device__ float g_kT[NB * HHv * MMv];   // projected k, transposed: [b][h][m]
__device__ float g_sc[NB * NQv * MMv];   // raw scores [b][n][m]
__device__ int   g_cnt[NB * 64];         // per-(b,qc) arrival tickets (self-reset)

__device__ __forceinline__ float ftanh(float x) {
    float y; asm("tanh.approx.f32 %0, %1;" : "=f"(y) : "f"(x)); return y;
}
__device__ __forceinline__ float fex2(float x) {
    float y; asm("ex2.approx.f32 %0, %1;" : "=f"(y) : "f"(x)); return y;
}
__device__ __forceinline__ unsigned long long pk2(float a, float b) {
    unsigned long long r; asm("mov.b64 %0, {%1, %2};" : "=l"(r) : "f"(a), "f"(b)); return r;
}
__device__ __forceinline__ void fma2(unsigned long long &d, unsigned long long a, unsigned long long b) {
    asm("fma.rn.f32x2 %0, %1, %2, %0;" : "+l"(d) : "l"(a), "l"(b));
}
__device__ __forceinline__ float2 up2(unsigned long long v) {
    float2 r; asm("mov.b64 {%0, %1}, %2;" : "=f"(r.x), "=f"(r.y) : "l"(v)); return r;
}

// ---------------------------------------------------------------------------
// Combined projection GEMM: 256 blocks (128 for q, 128 for kT).
// 64x64 tile, 256 threads, 4x4 micro-tile, f32x2 FMAs (the R2-proven body:
// best LDS-per-FMA ratio; L1 throughput ~30%).
// ---------------------------------------------------------------------------
__global__ __launch_bounds__(256) void proj_kernel(const float* __restrict__ query,
                                                   const float* __restrict__ key,
                                                   const float* __restrict__ Wq,
                                                   const float* __restrict__ Wk)
{
    __shared__ __align__(16) float As[16][68];
    __shared__ __align__(16) float Bs[16][64];

    int bid = blockIdx.x;
    int is_k = bid >> 7;
    int local = bid & 127;
    int row0 = (local >> 2) * 64;
    int col0 = (local & 3) * 64;
    const float* A = is_k ? key : query;
    const float* B = is_k ? Wk : Wq;

    int t = threadIdx.x;
    int tx = t & 15, ty = t >> 4;
    int arow = t >> 2, akq = t & 3;   // A-tile: 64 rows x 4 float4
    int bk = t >> 4, bh = t & 15;     // B-tile: 16 rows x 16 float4

    unsigned long long acc[4][2];
#pragma unroll
    for (int i = 0; i < 4; i++) { acc[i][0] = 0ull; acc[i][1] = 0ull; }

    for (int k0 = 0; k0 < DDv; k0 += 16) {
        float4 a4 = *(const float4*)(A + (row0 + arow) * DDv + k0 + akq * 4);
        float4 b4 = *(const float4*)(B + (k0 + bk) * HHv + col0 + bh * 4);
        As[akq * 4 + 0][arow] = a4.x;
        As[akq * 4 + 1][arow] = a4.y;
        As[akq * 4 + 2][arow] = a4.z;
        As[akq * 4 + 3][arow] = a4.w;
        *(float4*)&Bs[bk][bh * 4] = b4;
        __syncthreads();
#pragma unroll
        for (int k = 0; k < 16; k++) {
            const unsigned long long* br = (const unsigned long long*)&Bs[k][tx * 4];
            unsigned long long b0 = br[0], b1 = br[1];
#pragma unroll
            for (int i = 0; i < 4; i++) {
                float a = As[k][ty * 4 + i];
                unsigned long long aa = pk2(a, a);
                fma2(acc[i][0], aa, b0);
                fma2(acc[i][1], aa, b1);
            }
        }
        __syncthreads();
    }

#pragma unroll
    for (int i = 0; i < 4; i++) {
        int row = row0 + ty * 4 + i;
        int col = col0 + tx * 4;
        float2 c0 = up2(acc[i][0]);
        float2 c1 = up2(acc[i][1]);
        if (!is_k) {
            *(float4*)(g_q + row * HHv + col) = make_float4(c0.x, c0.y, c1.x, c1.y);
        } else {
            int bb = row >> 9, m = row & 511;
            float* base = g_kT + (bb * HHv) * MMv + m;
            base[(col + 0) * MMv] = c0.x;
            base[(col + 1) * MMv] = c0.y;
            base[(col + 2) * MMv] = c1.x;
            base[(col + 3) * MMv] = c1.y;
        }
    }
}

// ---------------------------------------------------------------------------
// Score + (drain-pattern) softmax/AV.
// Grid 1024 = b(4) x qc(64) x mc(4); 128 threads. Block computes the
// (8q x 128m) score tile; the LAST block of each (b,qc) (atomic ticket==3)
// then does softmax over the full 512-m row group + AV + output. No waiting:
// the epilogue block has already finished its own tile.
// ---------------------------------------------------------------------------
__global__ __launch_bounds__(128) void score_av_kernel(const float* __restrict__ Wv,
                                                       const float* __restrict__ value,
                                                       float* __restrict__ out)
{
    // Overlay: score phase uses qs+ws (9216B); epilogue reuses as sc (16384B)+inv_s
    __shared__ __align__(16) unsigned char SM[16448];
    __shared__ int is_last;

    float (*qs)[8] = (float(*)[8])SM;           // [h][q], 256x8 f32, rows 32B-aligned
    float* ws = (float*)(SM + 8192);            // 256 f32
    float (*sc)[MMv] = (float(*)[MMv])SM;       // [8][512] f32 (epilogue)
    float* inv_s = (float*)(SM + 16384);        // 8 f32

    int t = threadIdx.x;
    int bid = blockIdx.x;
    int mc = bid & 3;
    int qc = (bid >> 2) & 63;
    int b = bid >> 8;
    int n0 = qc * 8;
    int m = mc * 128 + t;

    // ---- Stage q (transposed to [h][q]) + W_v ----
#pragma unroll
    for (int r = 0; r < 4; r++) {
        int idx = t + r * 128;
        int q = idx & 7, c4 = idx >> 3;   // c4 in [0,64)
        float4 v = ((const float4*)(g_q + (b * NQv + n0 + q) * HHv))[c4];
        qs[c4 * 4 + 0][q] = v.x;
        qs[c4 * 4 + 1][q] = v.y;
        qs[c4 * 4 + 2][q] = v.z;
        qs[c4 * 4 + 3][q] = v.w;
    }
    if (t < 64) ((float4*)ws)[t] = ((const float4*)Wv)[t];
    __syncthreads();

    // ---- Score: MUFU.TANH bound ----
    float acc[8];
#pragma unroll
    for (int q = 0; q < 8; q++) acc[q] = 0.f;

    const float* kb = g_kT + (b * HHv) * MMv + m;
#pragma unroll 4
    for (int h = 0; h < HHv; h++) {
        float kv = kb[h * MMv];
        float wv = ws[h];
        float4 qa = *(const float4*)&qs[h][0];
        float4 qb = *(const float4*)&qs[h][4];
        acc[0] = fmaf(wv, ftanh(qa.x + kv), acc[0]);
        acc[1] = fmaf(wv, ftanh(qa.y + kv), acc[1]);
        acc[2] = fmaf(wv, ftanh(qa.z + kv), acc[2]);
        acc[3] = fmaf(wv, ftanh(qa.w + kv), acc[3]);
        acc[4] = fmaf(wv, ftanh(qb.x + kv), acc[4]);
        acc[5] = fmaf(wv, ftanh(qb.y + kv), acc[5]);
        acc[6] = fmaf(wv, ftanh(qb.z + kv), acc[6]);
        acc[7] = fmaf(wv, ftanh(qb.w + kv), acc[7]);
    }

#pragma unroll
    for (int q = 0; q < 8; q++)
        g_sc[(b * NQv + n0 + q) * MMv + m] = acc[q];

    // ---- Ticket: last arrival of this (b,qc) runs the epilogue ----
    __threadfence();   // release our score writes
    __syncthreads();
    if (t == 0) {
        int ticket = atomicAdd(&g_cnt[b * 64 + qc], 1);
        is_last = (ticket == 3);
    }
    __syncthreads();
    if (!is_last) return;
    __threadfence();   // acquire other blocks' score writes

    int w = t >> 5, lane = t & 31;

    // ---- Softmax: warp w handles rows 2w and 2w+1 ----
#pragma unroll
    for (int r = 0; r < 2; r++) {
        int row = w * 2 + r;
        const float* srow = g_sc + (b * NQv + n0 + row) * MMv;
        float vals[16];
        float vmax = -1e30f;
#pragma unroll
        for (int j = 0; j < 16; j++) {
            vals[j] = srow[lane + j * 32];
            vmax = fmaxf(vmax, vals[j]);
        }
#pragma unroll
        for (int o = 16; o > 0; o >>= 1)
            vmax = fmaxf(vmax, __shfl_xor_sync(0xffffffffu, vmax, o));
        float sum = 0.f;
#pragma unroll
        for (int j = 0; j < 16; j++) {
            float p = fex2((vals[j] - vmax) * 1.4426950408889634f);
            sc[row][lane + j * 32] = p;
            sum += p;
        }
#pragma unroll
        for (int o = 16; o > 0; o >>= 1)
            sum += __shfl_xor_sync(0xffffffffu, sum, o);
        if (lane == 0) inv_s[row] = 1.0f / sum;
    }
    __syncthreads();

    // ---- AV: thread owns v-pair vg; loop all 512 m, 4 at a time ----
    {
        int vg = t;   // 0..127 float2 columns of DV=256
        const float* vbase = value + (b * MMv) * DDv + vg * 2;
        unsigned long long oacc[8];
#pragma unroll
        for (int q = 0; q < 8; q++) oacc[q] = 0ull;

#pragma unroll 2
        for (int m4 = 0; m4 < MMv; m4 += 4) {
            float2 v0 = *(const float2*)(vbase + (m4 + 0) * DDv);
            float2 v1 = *(const float2*)(vbase + (m4 + 1) * DDv);
            float2 v2 = *(const float2*)(vbase + (m4 + 2) * DDv);
            float2 v3 = *(const float2*)(vbase + (m4 + 3) * DDv);
            unsigned long long w0 = pk2(v0.x, v0.y);
            unsigned long long w1 = pk2(v1.x, v1.y);
            unsigned long long w2 = pk2(v2.x, v2.y);
            unsigned long long w3 = pk2(v3.x, v3.y);
#pragma unroll
            for (int q = 0; q < 8; q++) {
                float4 p = *(const float4*)&sc[q][m4];
                fma2(oacc[q], pk2(p.x, p.x), w0);
                fma2(oacc[q], pk2(p.y, p.y), w1);
                fma2(oacc[q], pk2(p.z, p.z), w2);
                fma2(oacc[q], pk2(p.w, p.w), w3);
            }
        }

#pragma unroll
        for (int q = 0; q < 8; q++) {
            float2 o = up2(oacc[q]);
            float iv = inv_s[q];
            ((float2*)out)[(b * NQv + n0 + q) * 128 + vg] =
                make_float2(o.x * iv, o.y * iv);
        }
    }

    // Reset this group's ticket for the next graph replay (unique last block).
    __syncthreads();
    if (t == 0) atomicExch(&g_cnt[b * 64 + qc], 0);
}

extern "C" void kernel_launch(void* const* d_in, const int* in_sizes, int n_in,
                              void* d_out, int out_size)
{
    const float* query = (const float*)d_in[0];
    const float* key   = (const float*)d_in[1];
    const float* value = (const float*)d_in[2];
    const float* Wq    = (const float*)d_in[3];
    const float* Wk    = (const float*)d_in[4];
    const float* Wv    = (const float*)d_in[5];
    float* out = (float*)d_out;

    proj_kernel<<<256, 256>>>(query, key, Wq, Wk);
    score_av_kernel<<<1024, 128>>>(Wv, value, out);
}

// round 6
// speedup vs baseline: 1.9476x; 1.9476x over previous
#include <cuda_runtime.h>

// Fixed problem dims
#define NB 4
#define NQv 512
#define MMv 512
#define DDv 256
#define HHv 256

// Scratch (device globals: no allocations allowed)
__device__ float g_q[NB * NQv * HHv];    // projected q, [b*NQ+n][h]
__device__ float g_kT[NB * HHv * MMv];   // projected k, transposed: [b][h][m]
__device__ float g_sc[NB * NQv * MMv];   // raw scores [b][n][m]

__device__ __forceinline__ float ftanh(float x) {
    float y; asm("tanh.approx.f32 %0, %1;" : "=f"(y) : "f"(x)); return y;
}
__device__ __forceinline__ float fex2(float x) {
    float y; asm("ex2.approx.f32 %0, %1;" : "=f"(y) : "f"(x)); return y;
}
__device__ __forceinline__ unsigned long long pk2(float a, float b) {
    unsigned long long r; asm("mov.b64 %0, {%1, %2};" : "=l"(r) : "f"(a), "f"(b)); return r;
}
__device__ __forceinline__ void fma2(unsigned long long &d, unsigned long long a, unsigned long long b) {
    asm("fma.rn.f32x2 %0, %1, %2, %0;" : "+l"(d) : "l"(a), "l"(b));
}
__device__ __forceinline__ float2 up2(unsigned long long v) {
    float2 r; asm("mov.b64 {%0, %1}, %2;" : "=f"(r.x), "=f"(r.y) : "l"(v)); return r;
}

// ---------------------------------------------------------------------------
// Combined projection GEMM: 256 blocks (128 for q, 128 for kT).
// 64x64 tile, 256 threads, 4x4 micro-tile, f32x2 FMAs, double-buffered
// k-slabs (LDG for slab k+1 in flight during compute of slab k).
// ---------------------------------------------------------------------------
__global__ __launch_bounds__(256) void proj_kernel(const float* __restrict__ query,
                                                   const float* __restrict__ key,
                                                   const float* __restrict__ Wq,
                                                   const float* __restrict__ Wk)
{
    __shared__ __align__(16) float As[16][68];
    __shared__ __align__(16) float Bs[16][64];

    int bid = blockIdx.x;
    int is_k = bid >> 7;
    int local = bid & 127;
    int row0 = (local >> 2) * 64;
    int col0 = (local & 3) * 64;
    const float* A = is_k ? key : query;
    const float* B = is_k ? Wk : Wq;

    int t = threadIdx.x;
    int tx = t & 15, ty = t >> 4;
    int arow = t >> 2, akq = t & 3;   // A-tile: 64 rows x 4 float4
    int bk = t >> 4, bh = t & 15;     // B-tile: 16 rows x 16 float4

    const float* Aptr = A + (row0 + arow) * DDv + akq * 4;
    const float* Bptr = B + bk * HHv + col0 + bh * 4;

    unsigned long long acc[4][2];
#pragma unroll
    for (int i = 0; i < 4; i++) { acc[i][0] = 0ull; acc[i][1] = 0ull; }

    // Prefetch slab 0
    float4 a_n = *(const float4*)(Aptr);
    float4 b_n = *(const float4*)(Bptr);

    for (int k0 = 0; k0 < DDv; k0 += 16) {
        As[akq * 4 + 0][arow] = a_n.x;
        As[akq * 4 + 1][arow] = a_n.y;
        As[akq * 4 + 2][arow] = a_n.z;
        As[akq * 4 + 3][arow] = a_n.w;
        *(float4*)&Bs[bk][bh * 4] = b_n;
        __syncthreads();

        if (k0 + 16 < DDv) {
            a_n = *(const float4*)(Aptr + k0 + 16);
            b_n = *(const float4*)(Bptr + (k0 + 16) * HHv);
        }

#pragma unroll
        for (int k = 0; k < 16; k++) {
            const unsigned long long* br = (const unsigned long long*)&Bs[k][tx * 4];
            unsigned long long b0 = br[0], b1 = br[1];
#pragma unroll
            for (int i = 0; i < 4; i++) {
                float a = As[k][ty * 4 + i];
                unsigned long long aa = pk2(a, a);
                fma2(acc[i][0], aa, b0);
                fma2(acc[i][1], aa, b1);
            }
        }
        __syncthreads();
    }

#pragma unroll
    for (int i = 0; i < 4; i++) {
        int row = row0 + ty * 4 + i;
        int col = col0 + tx * 4;
        float2 c0 = up2(acc[i][0]);
        float2 c1 = up2(acc[i][1]);
        if (!is_k) {
            *(float4*)(g_q + row * HHv + col) = make_float4(c0.x, c0.y, c1.x, c1.y);
        } else {
            int bb = row >> 9, m = row & 511;
            float* base = g_kT + (bb * HHv) * MMv + m;
            base[(col + 0) * MMv] = c0.x;
            base[(col + 1) * MMv] = c0.y;
            base[(col + 2) * MMv] = c1.x;
            base[(col + 3) * MMv] = c1.y;
        }
    }
}

// ---------------------------------------------------------------------------
// Score kernel (R3-proven): sc[b,n,m] = sum_h w[h] * tanh(q[b,n,h] + k[b,m,h])
// Tile (8q x 128m), 128 threads. Grid = 1024 blocks. Lean footprint:
// smem 9.5KB, low regs -> high occupancy -> MUFU.TANH-paced (~70us).
// ---------------------------------------------------------------------------
__global__ __launch_bounds__(128) void score_kernel(const float* __restrict__ Wv)
{
    __shared__ __align__(16) float qs[8][264];  // [q][h]
    __shared__ __align__(16) float ws[HHv];

    int t = threadIdx.x;
    int bid = blockIdx.x;
    int mc = bid & 3;
    int qc = (bid >> 2) & 63;
    int b = bid >> 8;
    int n0 = qc * 8;
    int m = mc * 128 + t;

    // Stage 8 projected-q rows + W_v into smem
#pragma unroll
    for (int r = 0; r < 4; r++) {
        int idx = t + r * 128;
        int q = idx >> 6, c4 = idx & 63;
        float4 v = ((const float4*)(g_q + (b * NQv + n0 + q) * HHv))[c4];
        *(float4*)&qs[q][c4 * 4] = v;
    }
    if (t < 64) ((float4*)ws)[t] = ((const float4*)Wv)[t];
    __syncthreads();

    float acc[8];
#pragma unroll
    for (int q = 0; q < 8; q++) acc[q] = 0.f;

    const float* kb = g_kT + (b * HHv) * MMv + m;
#pragma unroll 4
    for (int h = 0; h < HHv; h++) {
        float kv = kb[h * MMv];
        float wv = ws[h];
#pragma unroll
        for (int q = 0; q < 8; q++)
            acc[q] = fmaf(wv, ftanh(qs[q][h] + kv), acc[q]);
    }

#pragma unroll
    for (int q = 0; q < 8; q++)
        g_sc[(b * NQv + n0 + q) * MMv + m] = acc[q];
}

// ---------------------------------------------------------------------------
// Softmax + AV (R3-proven): out[b,n,:] = softmax_m(sc[b,n,:]) @ value[b,:,:]
// Grid 256 = 4b x 64 query-chunks (8q). 256 threads.
// ---------------------------------------------------------------------------
__global__ __launch_bounds__(256) void softav_kernel(const float* __restrict__ value,
                                                     float* __restrict__ out)
{
    __shared__ __align__(16) float sc[8][MMv];
    __shared__ __align__(16) float2 ps[2][8][128];
    __shared__ float inv_s[8];

    int t = threadIdx.x;
    int b = (int)(blockIdx.x >> 6);
    int n0 = ((int)blockIdx.x & 63) << 3;
    int w = t >> 5, lane = t & 31;

    // ---- Softmax: warp w handles query row w, reading scores from global ----
    {
        const float* srow = g_sc + (b * NQv + n0 + w) * MMv;
        float vals[16];
        float vmax = -1e30f;
#pragma unroll
        for (int j = 0; j < 16; j++) {
            vals[j] = srow[lane + j * 32];
            vmax = fmaxf(vmax, vals[j]);
        }
#pragma unroll
        for (int o = 16; o > 0; o >>= 1)
            vmax = fmaxf(vmax, __shfl_xor_sync(0xffffffffu, vmax, o));
        float sum = 0.f;
#pragma unroll
        for (int j = 0; j < 16; j++) {
            float p = fex2((vals[j] - vmax) * 1.4426950408889634f);
            sc[w][lane + j * 32] = p;
            sum += p;
        }
#pragma unroll
        for (int o = 16; o > 0; o >>= 1)
            sum += __shfl_xor_sync(0xffffffffu, sum, o);
        if (lane == 0) inv_s[w] = 1.0f / sum;
    }
    __syncthreads();

    // ---- AV: out[q,v] = (sum_m p[q,m] * value[m,v]) * inv_sum[q] ----
    int mg = t >> 7;          // m-split group (0 or 1)
    int vg = t & 127;         // v-pair index
    const float* vbase = value + (b * MMv + mg * 256) * DDv + vg * 2;
    unsigned long long acc[8];
#pragma unroll
    for (int q = 0; q < 8; q++) acc[q] = 0ull;
#pragma unroll 4
    for (int mm = 0; mm < 256; mm++) {
        float2 vv = *(const float2*)(vbase + mm * DDv);
        unsigned long long v2 = pk2(vv.x, vv.y);
        int m = mg * 256 + mm;
#pragma unroll
        for (int q = 0; q < 8; q++) {
            float a = sc[q][m];
            fma2(acc[q], pk2(a, a), v2);
        }
    }
#pragma unroll
    for (int q = 0; q < 8; q++) ps[mg][q][vg] = up2(acc[q]);
    __syncthreads();

    // Reduce 2 m-partials, scale by 1/sum, write out (1024 f2 / 256 thr = 4 it)
#pragma unroll
    for (int r = 0; r < 4; r++) {
        int p = t + r * 256;
        int q = p >> 7, v2i = p & 127;
        float2 s0 = ps[0][q][v2i], s1 = ps[1][q][v2i];
        float iv = inv_s[q];
        float2 o = make_float2((s0.x + s1.x) * iv, (s0.y + s1.y) * iv);
        ((float2*)out)[(b * NQv + n0 + q) * 128 + v2i] = o;
    }
}

extern "C" void kernel_launch(void* const* d_in, const int* in_sizes, int n_in,
                              void* d_out, int out_size)
{
    const float* query = (const float*)d_in[0];
    const float* key   = (const float*)d_in[1];
    const float* value = (const float*)d_in[2];
    const float* Wq    = (const float*)d_in[3];
    const float* Wk    = (const float*)d_in[4];
    const float* Wv    = (const float*)d_in[5];
    float* out = (float*)d_out;

    proj_kernel<<<256, 256>>>(query, key, Wq, Wk);
    score_kernel<<<1024, 128>>>(Wv);
    softav_kernel<<<256, 256>>>(value, out);
}